// round 7
// baseline (speedup 1.0000x reference)
#include <cuda_runtime.h>
#include <math.h>

#define MDIM 4096
#define NT 32             // 32 tile-rows of 128
#define TILE 128
#define NBLK 528          // upper triangle tiles
#define RES 104           // rows of each tile resident in SMEM (rest streamed from L2)
#define B1f 0.9f
#define B2f 0.999f
#define EPSV 1e-8f
#define LRV 0.1f
#define NSTEPS 199

// dynamic smem layout (floats): [tile RES*128][xsI 128][xsJ 128][colj 128]
#define SM_TILE_F (RES * TILE)              // 13312
#define SM_XSI    (SM_TILE_F)
#define SM_XSJ    (SM_XSI + TILE)
#define SM_COLJ   (SM_XSJ + TILE)
#define SM_FLOATS (SM_COLJ + TILE)          // 13696 floats = 54784 B

// ---- scratch (__device__ globals; no allocation) ----
__device__ float d_Qs[(size_t)MDIM * MDIM];
__device__ float d_g[(NSTEPS + 1)][MDIM];
__device__ float d_W[2][MDIM];
__device__ float d_MT[2][MDIM];
__device__ float d_VT[2][MDIM];
__device__ float d_steplr[NSTEPS + 1];
__device__ float d_invb2[NSTEPS + 1];
__device__ unsigned int d_barcnt;

// ---------------------------------------------------------------------------
__global__ void prep_qs_kernel(const float* __restrict__ va) {
    __shared__ float tile[32][33];
    int bx = blockIdx.x * 32, by = blockIdx.y * 32;
    if (bx + 32 <= by) return;                   // upper-triangle blocks only
    int tx = threadIdx.x, ty = threadIdx.y;
    tile[ty][tx] = va[(size_t)(bx + ty) * MDIM + (by + tx)];
    __syncthreads();
    size_t idx = (size_t)(by + ty) * MDIM + (bx + tx);
    d_Qs[idx] = 0.5f * (va[idx] + tile[tx][ty]);
}

// ---------------------------------------------------------------------------
__global__ void init_kernel() {
    int i = blockIdx.x * blockDim.x + threadIdx.x;
    if (i < MDIM) {
        d_W[0][i] = 1.0f;  d_W[1][i] = 1.0f;
        d_MT[0][i] = 0.0f; d_MT[1][i] = 0.0f;
        d_VT[0][i] = 0.0f; d_VT[1][i] = 0.0f;
    }
    if (i == 0) d_barcnt = 0u;
    if (i <= NSTEPS) {
        if (i == 0) { d_steplr[0] = 0.0f; d_invb2[0] = 0.0f; }
        else {
            double bc1 = 1.0 - pow(0.9,   (double)i);
            double bc2 = 1.0 - pow(0.999, (double)i);
            d_steplr[i] = (float)((double)LRV / bc1);
            d_invb2[i]  = (float)(1.0 / sqrt(bc2));
        }
    }
    int total = (NSTEPS + 1) * MDIM;
    for (int j = i; j < total; j += gridDim.x * blockDim.x)
        (&d_g[0][0])[j] = 0.0f;
}

// ---------------------------------------------------------------------------
// Persistent kernel, SMEM-resident tiles. 528 blocks, 4/SM, grid barrier/step.
// Warp w handles local rows r = w + 8k, k=0..15; k<=12 from SMEM, k>=13 from L2.
// ---------------------------------------------------------------------------
__global__ __launch_bounds__(256, 4)
void persist_kernel(const float* __restrict__ mean,
                    float* __restrict__ out,
                    float* __restrict__ g_base)
{
    extern __shared__ float sm[];
    float* smTile = sm;
    float* xsI  = sm + SM_XSI;
    float* xsJ  = sm + SM_XSJ;
    float* colj = sm + SM_COLJ;

    // block -> upper-triangle tile (ti <= tj)
    int b = blockIdx.x;
    int ti = 0, rem = b;
    while (rem >= NT - ti) { rem -= NT - ti; ++ti; }
    int tj = ti + rem;
    const int I = ti * TILE, J = tj * TILE;
    const bool diag = (ti == tj);

    int tid = threadIdx.x, w = tid >> 5, lane = tid & 31;
    const float4* __restrict__ Q4 = reinterpret_cast<const float4*>(d_Qs);
    float4* smTile4 = reinterpret_cast<float4*>(smTile);

    // ---- one-time: load resident rows [0,RES) of this tile into SMEM ----
    for (int idx = tid; idx < RES * (TILE / 4); idx += 256) {
        int r  = idx >> 5;          // / 32
        int c4 = idx & 31;
        smTile4[idx] = Q4[(size_t)(I + r) * (MDIM / 4) + (J / 4) + c4];
    }
    __syncthreads();

    // streamed-row global indices for this warp (rows w+104, w+112, w+120)
    size_t qrow0 = (size_t)(I + w + 104) * (MDIM / 4) + (J / 4) + lane;
    size_t qrow1 = (size_t)(I + w + 112) * (MDIM / 4) + (J / 4) + lane;
    size_t qrow2 = (size_t)(I + w + 120) * (MDIM / 4) + (J / 4) + lane;

    for (int s = 1; s <= NSTEPS; ++s) {
        int t = s - 1;
        int p = t & 1, q = p ^ 1;
        float steplr = d_steplr[t];
        float invb2  = d_invb2[t];
        const float* g_prev = g_base + (size_t)t * MDIM;
        float*       g_out  = g_base + (size_t)s * MDIM;

        // issue streamed Qs loads early (constant data: no dependence on g)
        float4 sq0 = __ldg(&Q4[qrow0]);
        float4 sq1 = __ldg(&Q4[qrow1]);
        float4 sq2 = __ldg(&Q4[qrow2]);

        // ---- prologue: duplicated Adam step t, build x; zero colj ----
        {
            int row = (tid < TILE) ? (I + tid) : (J + tid - TILE);
            float g  = __ldcg(&g_prev[row]);
            float mt = B1f * d_MT[p][row] + (1.0f - B1f) * g;
            float vt = B2f * d_VT[p][row] + (1.0f - B2f) * g * g;
            float wn = d_W[p][row] - steplr * mt / (sqrtf(vt) * invb2 + EPSV);
            d_W[q][row]  = wn;
            d_MT[q][row] = mt;
            d_VT[q][row] = vt;
            float x = wn - mean[row];
            if (tid < TILE) { xsI[tid] = x; colj[tid] = 0.0f; }
            else            { xsJ[tid - TILE] = x; }
            if (diag && tid >= TILE) xsI[tid - TILE] = x;  // harmless dup path
        }
        if (diag && tid < TILE) xsJ[tid] = xsI[tid];
        __syncthreads();

        // ---- SYMV: 13 SMEM rows + 3 L2 rows per warp ----
        float4 xj = reinterpret_cast<const float4*>(xsJ)[lane];
        float rp[16];
        float4 ca = make_float4(0.f, 0.f, 0.f, 0.f);

        if (!diag) {
            #pragma unroll
            for (int k = 0; k < 16; ++k) {
                int r = w + 8 * k;
                float4 qv;
                if (k <= 12)      qv = smTile4[r * (TILE / 4) + lane];
                else if (k == 13) qv = sq0;
                else if (k == 14) qv = sq1;
                else              qv = sq2;
                float xi = xsI[r];
                rp[k] = qv.x * xj.x + qv.y * xj.y + qv.z * xj.z + qv.w * xj.w;
                ca.x = fmaf(qv.x, xi, ca.x);
                ca.y = fmaf(qv.y, xi, ca.y);
                ca.z = fmaf(qv.z, xi, ca.z);
                ca.w = fmaf(qv.w, xi, ca.w);
            }
        } else {
            int c0 = 4 * lane;
            #pragma unroll
            for (int k = 0; k < 16; ++k) {
                int r = w + 8 * k;
                float4 qv;
                if (k <= 12)      qv = smTile4[r * (TILE / 4) + lane];
                else if (k == 13) qv = sq0;
                else if (k == 14) qv = sq1;
                else              qv = sq2;
                float xi = xsI[r];
                float r0 = (c0 + 0 >= r) ? qv.x * xj.x : 0.f;
                float r1 = (c0 + 1 >= r) ? qv.y * xj.y : 0.f;
                float r2 = (c0 + 2 >= r) ? qv.z * xj.z : 0.f;
                float r3 = (c0 + 3 >= r) ? qv.w * xj.w : 0.f;
                rp[k] = (r0 + r1) + (r2 + r3);
                if (c0 + 0 > r) ca.x = fmaf(qv.x, xi, ca.x);
                if (c0 + 1 > r) ca.y = fmaf(qv.y, xi, ca.y);
                if (c0 + 2 > r) ca.z = fmaf(qv.z, xi, ca.z);
                if (c0 + 3 > r) ca.w = fmaf(qv.w, xi, ca.w);
            }
        }

        // ---- reductions (off load path) ----
        #pragma unroll
        for (int k = 0; k < 16; ++k) {
            #pragma unroll
            for (int off = 16; off > 0; off >>= 1)
                rp[k] += __shfl_xor_sync(0xFFFFFFFFu, rp[k], off);
        }
        if (lane < 16)
            atomicAdd(&g_out[I + w + 8 * lane], rp[lane]);

        atomicAdd(&colj[4 * lane + 0], ca.x);
        atomicAdd(&colj[4 * lane + 1], ca.y);
        atomicAdd(&colj[4 * lane + 2], ca.z);
        atomicAdd(&colj[4 * lane + 3], ca.w);
        __syncthreads();
        if (tid < TILE)
            atomicAdd(&g_out[J + tid], colj[tid]);
        __syncthreads();

        // ---- grid barrier ----
        if (tid == 0) {
            __threadfence();
            atomicAdd(&d_barcnt, 1u);
            unsigned target = (unsigned)s * NBLK;
            while (*(volatile unsigned int*)&d_barcnt < target) { }
        }
        __syncthreads();
    }

    // ---- final Adam step t=199 -> out (state parity 1) ----
    {
        float steplr = d_steplr[NSTEPS];
        float invb2  = d_invb2[NSTEPS];
        const float* g_last = g_base + (size_t)NSTEPS * MDIM;
        int gid = blockIdx.x * 256 + tid;
        if (gid < MDIM) {
            float g  = __ldcg(&g_last[gid]);
            float mt = B1f * d_MT[1][gid] + (1.0f - B1f) * g;
            float vt = B2f * d_VT[1][gid] + (1.0f - B2f) * g * g;
            out[gid] = d_W[1][gid] - steplr * mt / (sqrtf(vt) * invb2 + EPSV);
        }
    }
}

// ---------------------------------------------------------------------------
extern "C" void kernel_launch(void* const* d_in, const int* in_sizes, int n_in,
                              void* d_out, int out_size) {
    const float* mean = (const float*)d_in[0];
    const float* va   = (const float*)d_in[1];
    float* out = (float*)d_out;
    (void)in_sizes; (void)n_in; (void)out_size;

    float* g_base; cudaGetSymbolAddress((void**)&g_base, d_g);

    static int attr_set = 0;
    if (!attr_set) {
        cudaFuncSetAttribute(persist_kernel,
                             cudaFuncAttributeMaxDynamicSharedMemorySize,
                             SM_FLOATS * sizeof(float));
        attr_set = 1;
    }

    dim3 tb(32, 32), tg(MDIM / 32, MDIM / 32);
    prep_qs_kernel<<<tg, tb>>>(va);
    init_kernel<<<128, 256>>>();
    persist_kernel<<<NBLK, 256, SM_FLOATS * sizeof(float)>>>(mean, out, g_base);
}

// round 8
// speedup vs baseline: 1.0895x; 1.0895x over previous
#include <cuda_runtime.h>
#include <math.h>

#define MDIM 4096
#define NT 32            // 32 tile-rows of 128
#define TILE 128
#define NTILES 528       // upper triangle: 32*33/2
#define B1f 0.9f
#define B2f 0.999f
#define EPSV 1e-8f
#define LRV 0.1f
#define NSTEPS 199

// ---- scratch (__device__ globals; no allocation) ----
__device__ float d_Qs[(size_t)MDIM * MDIM];      // symmetrized fp32 (upper half valid)
__device__ float d_g[(NSTEPS + 1)][MDIM];        // per-step g buffers (g[0] stays 0)
__device__ float d_W[2][MDIM];
__device__ float d_MT[2][MDIM];
__device__ float d_VT[2][MDIM];

// ---------------------------------------------------------------------------
__global__ void prep_qs_kernel(const float* __restrict__ va) {
    __shared__ float tile[32][33];
    int bx = blockIdx.x * 32, by = blockIdx.y * 32;
    if (bx + 32 <= by) return;                   // upper-triangle blocks only
    int tx = threadIdx.x, ty = threadIdx.y;
    tile[ty][tx] = va[(size_t)(bx + ty) * MDIM + (by + tx)];
    __syncthreads();
    size_t idx = (size_t)(by + ty) * MDIM + (bx + tx);
    d_Qs[idx] = 0.5f * (va[idx] + tile[tx][ty]);
}

// ---------------------------------------------------------------------------
__global__ void init_kernel() {
    int i = blockIdx.x * blockDim.x + threadIdx.x;
    if (i < MDIM) {
        d_W[0][i] = 1.0f;  d_W[1][i] = 1.0f;
        d_MT[0][i] = 0.0f; d_MT[1][i] = 0.0f;
        d_VT[0][i] = 0.0f; d_VT[1][i] = 0.0f;
    }
    int total = (NSTEPS + 1) * MDIM;
    for (int j = i; j < total; j += gridDim.x * blockDim.x)
        (&d_g[0][0])[j] = 0.0f;
}

// ---------------------------------------------------------------------------
// Launch s: fused Adam prologue (step s-1) + upper-triangle SYMV tile.
// Row partials reduced by shuffles (no smem); col partials via per-warp smem.
// ---------------------------------------------------------------------------
__global__ __launch_bounds__(256, 4)
void adam_step_kernel(const float* __restrict__ mean,
                      const float* __restrict__ g_prev,
                      float* __restrict__ g_out,
                      int p, float step_lr, float inv_sqrt_bc2)
{
    __shared__ float xsI[TILE];
    __shared__ float xsJ[TILE];
    __shared__ float colp[8][TILE];    // per-warp col partials (plain stores)

    // map block -> upper-triangle tile (ti <= tj)
    int b = blockIdx.x;
    int ti = 0, rem = b;
    while (rem >= NT - ti) { rem -= NT - ti; ++ti; }
    int tj = ti + rem;
    const int I = ti * TILE, J = tj * TILE;
    const bool diag = (ti == tj);

    int tid = threadIdx.x, w = tid >> 5, lane = tid & 31;
    int q = p ^ 1;

    // ---- prologue: Adam update (duplicated, deterministic) + build x ----
    {
        int row = -1;
        if (diag) { if (tid < TILE) row = I + tid; }
        else      { row = (tid < TILE) ? (I + tid) : (J + tid - TILE); }
        if (row >= 0) {
            float g  = g_prev[row];
            float mt = B1f * d_MT[p][row] + (1.0f - B1f) * g;
            float vt = B2f * d_VT[p][row] + (1.0f - B2f) * g * g;
            float wn = d_W[p][row] - step_lr * mt / (sqrtf(vt) * inv_sqrt_bc2 + EPSV);
            d_W[q][row]  = wn;
            d_MT[q][row] = mt;
            d_VT[q][row] = vt;
            float x = wn - mean[row];
            if (tid < TILE) { xsI[tid] = x; if (diag) xsJ[tid] = x; }
            else            { xsJ[tid - TILE] = x; }
        }
    }
    __syncthreads();

    // ---- SYMV tile: warp owns rows w*16..w*16+15; lane owns one float4 ----
    const float4* __restrict__ Q4 = reinterpret_cast<const float4*>(d_Qs);
    size_t qbase = (size_t)(I + w * 16) * (MDIM / 4) + (J / 4) + lane;
    float4 xj = reinterpret_cast<const float4*>(xsJ)[lane];
    float  rp[16];
    float4 ca = make_float4(0.f, 0.f, 0.f, 0.f);

    if (!diag) {
        #pragma unroll
        for (int rr = 0; rr < 16; rr += 8) {
            float4 qv[8];
            #pragma unroll
            for (int k = 0; k < 8; ++k)
                qv[k] = Q4[qbase + (size_t)(rr + k) * (MDIM / 4)];
            #pragma unroll
            for (int k = 0; k < 8; ++k) {
                float xi = xsI[w * 16 + rr + k];
                rp[rr + k] = qv[k].x * xj.x + qv[k].y * xj.y
                           + qv[k].z * xj.z + qv[k].w * xj.w;
                ca.x = fmaf(qv[k].x, xi, ca.x);
                ca.y = fmaf(qv[k].y, xi, ca.y);
                ca.z = fmaf(qv[k].z, xi, ca.z);
                ca.w = fmaf(qv[k].w, xi, ca.w);
            }
        }
    } else {
        int c0 = 4 * lane;
        #pragma unroll
        for (int rr = 0; rr < 16; rr += 8) {
            float4 qv[8];
            #pragma unroll
            for (int k = 0; k < 8; ++k)
                qv[k] = Q4[qbase + (size_t)(rr + k) * (MDIM / 4)];
            #pragma unroll
            for (int k = 0; k < 8; ++k) {
                int lr = w * 16 + rr + k;
                float xi = xsI[lr];
                float r0 = (c0 + 0 >= lr) ? qv[k].x * xj.x : 0.f;
                float r1 = (c0 + 1 >= lr) ? qv[k].y * xj.y : 0.f;
                float r2 = (c0 + 2 >= lr) ? qv[k].z * xj.z : 0.f;
                float r3 = (c0 + 3 >= lr) ? qv[k].w * xj.w : 0.f;
                rp[rr + k] = (r0 + r1) + (r2 + r3);
                if (c0 + 0 > lr) ca.x = fmaf(qv[k].x, xi, ca.x);
                if (c0 + 1 > lr) ca.y = fmaf(qv[k].y, xi, ca.y);
                if (c0 + 2 > lr) ca.z = fmaf(qv[k].z, xi, ca.z);
                if (c0 + 3 > lr) ca.w = fmaf(qv[k].w, xi, ca.w);
            }
        }
    }

    // ---- row reduction: butterfly shuffles, then 16 atomics from lane<16 ----
    #pragma unroll
    for (int k = 0; k < 16; ++k) {
        #pragma unroll
        for (int off = 16; off > 0; off >>= 1)
            rp[k] += __shfl_xor_sync(0xFFFFFFFFu, rp[k], off);
    }
    if (lane < 16)
        atomicAdd(&g_out[I + w * 16 + lane], rp[lane]);

    // ---- col reduction: per-warp plain stores, one sync, 8-way add ----
    reinterpret_cast<float4*>(colp[w])[lane] = ca;
    __syncthreads();
    if (tid < TILE) {
        float acc = 0.f;
        #pragma unroll
        for (int ww = 0; ww < 8; ++ww) acc += colp[ww][tid];
        atomicAdd(&g_out[J + tid], acc);
    }
}

// ---------------------------------------------------------------------------
__global__ void finish_kernel(float* __restrict__ out,
                              const float* __restrict__ g_last,
                              int p, float step_lr, float inv_sqrt_bc2) {
    int i = blockIdx.x * blockDim.x + threadIdx.x;
    if (i < MDIM) {
        float g  = g_last[i];
        float mt = B1f * d_MT[p][i] + (1.0f - B1f) * g;
        float vt = B2f * d_VT[p][i] + (1.0f - B2f) * g * g;
        out[i] = d_W[p][i] - step_lr * mt / (sqrtf(vt) * inv_sqrt_bc2 + EPSV);
    }
}

// ---------------------------------------------------------------------------
extern "C" void kernel_launch(void* const* d_in, const int* in_sizes, int n_in,
                              void* d_out, int out_size) {
    const float* mean = (const float*)d_in[0];
    const float* va   = (const float*)d_in[1];
    float* out = (float*)d_out;
    (void)in_sizes; (void)n_in; (void)out_size;

    float* g_base; cudaGetSymbolAddress((void**)&g_base, d_g);

    dim3 tb(32, 32), tg(MDIM / 32, MDIM / 32);
    prep_qs_kernel<<<tg, tb>>>(va);
    init_kernel<<<128, 256>>>();

    for (int s = 1; s <= NSTEPS; ++s) {
        int t = s - 1;
        float step_lr = 0.f, inv_b2 = 0.f;
        if (t >= 1) {
            double bc1 = 1.0 - pow(0.9,   (double)t);
            double bc2 = 1.0 - pow(0.999, (double)t);
            step_lr = (float)((double)LRV / bc1);
            inv_b2  = (float)(1.0 / sqrt(bc2));
        }
        int p = (s - 1) & 1;
        adam_step_kernel<<<NTILES, 256>>>(mean,
                                          g_base + (size_t)(s - 1) * MDIM,
                                          g_base + (size_t)s * MDIM,
                                          p, step_lr, inv_b2);
    }

    {
        int t = NSTEPS;
        double bc1 = 1.0 - pow(0.9,   (double)t);
        double bc2 = 1.0 - pow(0.999, (double)t);
        float step_lr = (float)((double)LRV / bc1);
        float inv_b2  = (float)(1.0 / sqrt(bc2));
        finish_kernel<<<(MDIM + 255) / 256, 256>>>(out,
                                                   g_base + (size_t)NSTEPS * MDIM,
                                                   NSTEPS & 1, step_lr, inv_b2);
    }
}